// round 11
// baseline (speedup 1.0000x reference)
#include <cuda_runtime.h>

#define HH 256
#define WW 256
#define HW 65536
#define BS 8
#define IC 16
#define OC 32
#define NSTEPS 7
#define TILES 2

typedef unsigned long long u64;

// Scratch (static device globals — no runtime allocation).
__device__ __align__(16) float  g_raw[BS * OC * HW];   // conv output (planar)
__device__ __align__(16) float2 g_fA[BS * IC * HW];    // interleaved flow ping
__device__ __align__(16) float2 g_fB[BS * IC * HW];    // interleaved flow pong
__device__ float g_part[2][OC][2048];                  // per-block partial (sum, sumsq)
__device__ float g_affa[OC];                           // BN affine scale (incl. 1/128)
__device__ float g_affb[OC];                           // BN affine shift (incl. 1/128)

__device__ __forceinline__ u64 pack2(float lo, float hi) {
    u64 r; asm("mov.b64 %0, {%1, %2};" : "=l"(r) : "f"(lo), "f"(hi)); return r;
}
__device__ __forceinline__ void unpack2(u64 v, float& lo, float& hi) {
    asm("mov.b64 {%0, %1}, %2;" : "=f"(lo), "=f"(hi) : "l"(v));
}
__device__ __forceinline__ u64 ffma2(u64 a, u64 b, u64 c) {
    u64 d; asm("fma.rn.f32x2 %0, %1, %2, %3;" : "=l"(d) : "l"(a), "l"(b), "l"(c)); return d;
}

// ---------------------------------------------------------------------------
// Conv 3x3 (16->32, pad 1) via packed f32x2 FMA + deterministic stats.
// ---------------------------------------------------------------------------
__global__ __launch_bounds__(256) void conv_kernel(const float* __restrict__ f,
                                                   const float* __restrict__ vw,
                                                   const float* __restrict__ vb) {
    __shared__ float ft[IC * 10 * 34];
    __shared__ float ws[OC * 144];

    const int tid  = threadIdx.x;
    const int lane = tid & 31;
    const int wid  = tid >> 5;
    const int x0   = blockIdx.x * 32;
    const int y0   = blockIdx.y * 8;
    const int b    = blockIdx.z;

    for (int i = tid; i < OC * 144; i += 256) ws[i] = vw[i];

    const float* fb = f + (size_t)b * IC * HW;
    for (int i = tid; i < IC * 10 * 34; i += 256) {
        int ic = i / 340;
        int rem = i % 340;
        int r = rem / 34, cc = rem % 34;
        int yy = y0 - 1 + r, xx = x0 - 1 + cc;
        float v = 0.f;
        if (yy >= 0 && yy < HH && xx >= 0 && xx < WW) v = fb[ic * HW + yy * WW + xx];
        ft[i] = v;
    }
    __syncthreads();

    const int oc0 = wid * 4;
    u64 acc[4][4];   // 4 oc x 4 pixel-pairs (8 rows)
#pragma unroll
    for (int i = 0; i < 4; i++) {
        float bias = vb[oc0 + i];
        u64 bp = pack2(bias, bias);
#pragma unroll
        for (int j = 0; j < 4; j++) acc[i][j] = bp;
    }

    for (int ic = 0; ic < IC; ic++) {
        const float* ftc = ft + ic * 340;
#pragma unroll
        for (int kx = 0; kx < 3; kx++) {
            float col[10];
#pragma unroll
            for (int r = 0; r < 10; r++) col[r] = ftc[r * 34 + lane + kx];
            u64 colp[9];
#pragma unroll
            for (int r = 0; r < 9; r++) colp[r] = pack2(col[r], col[r + 1]);
#pragma unroll
            for (int i = 0; i < 4; i++) {
#pragma unroll
                for (int ky = 0; ky < 3; ky++) {
                    float w = ws[(oc0 + i) * 144 + ic * 9 + ky * 3 + kx];
                    u64 wd = pack2(w, w);
#pragma unroll
                    for (int j = 0; j < 4; j++)
                        acc[i][j] = ffma2(colp[2 * j + ky], wd, acc[i][j]);
                }
            }
        }
    }

    const int blk = (b * (int)gridDim.y + blockIdx.y) * (int)gridDim.x + blockIdx.x;
#pragma unroll
    for (int i = 0; i < 4; i++) {
        float s = 0.f, s2 = 0.f;
        float* dst = g_raw + (size_t)(b * OC + oc0 + i) * HW + y0 * WW + x0 + lane;
#pragma unroll
        for (int j = 0; j < 4; j++) {
            float v0, v1;
            unpack2(acc[i][j], v0, v1);
            dst[(2 * j) * WW] = v0;
            dst[(2 * j + 1) * WW] = v1;
            s += v0 + v1;
            s2 += v0 * v0 + v1 * v1;
        }
#pragma unroll
        for (int off = 16; off > 0; off >>= 1) {
            s  += __shfl_down_sync(0xffffffffu, s, off);
            s2 += __shfl_down_sync(0xffffffffu, s2, off);
        }
        if (lane == 0) {
            g_part[0][oc0 + i][blk] = s;
            g_part[1][oc0 + i][blk] = s2;
        }
    }
}

// ---------------------------------------------------------------------------
// Reduce partials -> BN affine, folded with 1/2^NSTEPS.
// ---------------------------------------------------------------------------
__global__ __launch_bounds__(256) void stats_kernel(const float* __restrict__ gamma,
                                                    const float* __restrict__ beta) {
    __shared__ float sm[256], sm2[256];
    const int ch = blockIdx.x, tid = threadIdx.x;
    float s = 0.f, s2 = 0.f;
    for (int i = tid; i < 2048; i += 256) {
        s += g_part[0][ch][i];
        s2 += g_part[1][ch][i];
    }
    sm[tid] = s; sm2[tid] = s2;
    __syncthreads();
    for (int off = 128; off > 0; off >>= 1) {
        if (tid < off) { sm[tid] += sm[tid + off]; sm2[tid] += sm2[tid + off]; }
        __syncthreads();
    }
    if (tid == 0) {
        const float n = (float)(BS * HW);
        float mean = sm[0] / n;
        float var = sm2[0] / n - mean * mean;
        float r = rsqrtf(var + 1e-5f);
        const float scale = 1.0f / 128.0f;
        g_affa[ch] = gamma[ch] * r * scale;
        g_affb[ch] = (beta[ch] - gamma[ch] * mean * r) * scale;
    }
}

// ---------------------------------------------------------------------------
// Bilinear setup with clamp+mask: indices always in-bounds (clamped), validity
// folded into the weights. All 4 tap loads become unconditional -> MLP 4.
// Bitwise-equal to zero-padded bilinear (invalid taps get weight 0).
// ---------------------------------------------------------------------------
__device__ __forceinline__ void bilin_setup(float py, float px,
                                            int& i00, int& i01, int& i10, int& i11,
                                            float& w00, float& w01, float& w10, float& w11) {
    float yf = floorf(py), xf = floorf(px);
    float fy1 = py - yf, fx1 = px - xf;
    int yi = (int)yf, xi = (int)xf;
    float ay0 = ((unsigned)yi       < (unsigned)HH) ? 1.f - fy1 : 0.f;
    float ay1 = ((unsigned)(yi + 1) < (unsigned)HH) ? fy1       : 0.f;
    float ax0 = ((unsigned)xi       < (unsigned)WW) ? 1.f - fx1 : 0.f;
    float ax1 = ((unsigned)(xi + 1) < (unsigned)WW) ? fx1       : 0.f;
    int y0 = min(max(yi, 0), HH - 1),     y1 = min(max(yi + 1, 0), HH - 1);
    int x0 = min(max(xi, 0), WW - 1),     x1 = min(max(xi + 1, 0), WW - 1);
    i00 = (y0 << 8) | x0; i01 = (y0 << 8) | x1;
    i10 = (y1 << 8) | x0; i11 = (y1 << 8) | x1;
    w00 = ay0 * ax0; w01 = ay0 * ax1; w10 = ay1 * ax0; w11 = ay1 * ax1;
}

__device__ __forceinline__ void gather2c(const float2* __restrict__ pl,
                                         float py, float px, float& gy, float& gx) {
    int i00, i01, i10, i11; float w00, w01, w10, w11;
    bilin_setup(py, px, i00, i01, i10, i11, w00, w01, w10, w11);
    float2 v00 = pl[i00], v01 = pl[i01], v10 = pl[i10], v11 = pl[i11];
    gy = w00 * v00.x + w01 * v01.x + w10 * v10.x + w11 * v11.x;
    gx = w00 * v00.y + w01 * v01.y + w10 * v10.y + w11 * v11.y;
}

__device__ __forceinline__ float gather1c(const float* __restrict__ pl,
                                          float py, float px) {
    int i00, i01, i10, i11; float w00, w01, w10, w11;
    bilin_setup(py, px, i00, i01, i10, i11, w00, w01, w10, w11);
    float v00 = pl[i00], v01 = pl[i01], v10 = pl[i10], v11 = pl[i11];
    return w00 * v00 + w01 * v01 + w10 * v10 + w11 * v11;
}

// ---------------------------------------------------------------------------
// One fused scaling-and-squaring step, two-phase block structure.
// TILES tiles of 32 consecutive pixels per block (grid 8192), 512 threads.
// Phase 1: thread (c, px) integrates flow channel c at pixel px (clamp+mask
//          gathers, unconditional tap loads), stores the new flow, samples f
//          into smem. Phase 2: thread (o, px) mixes 16 smem samples with fuse
//          weights, RMWs out. FIRST applies BN affine per tap and writes out
//          with bias; LAST skips the never-read flow store.
// ---------------------------------------------------------------------------
template <bool FIRST, bool LAST>
__global__ __launch_bounds__(512) void step_kernel(const float* __restrict__ f,
                                                   const float* __restrict__ fw,
                                                   const float* __restrict__ fbias,
                                                   float* __restrict__ out,
                                                   int step) {
    __shared__ float ws[256];        // [o][c]
    __shared__ float fb_s[16];
    __shared__ float sm_m[16][33];   // [c][px] padded

    const int tid = threadIdx.x;
    if (tid < 256) {
        int o = tid >> 4, c = tid & 15;
        ws[o * 16 + c] = fw[(o * 16 + c) * NSTEPS + step];
    }
    if (tid < 16) fb_s[tid] = fbias[tid];
    __syncthreads();

    const int c_  = tid >> 5;
    const int pj  = tid & 31;

#pragma unroll
    for (int it = 0; it < TILES; it++) {
        const int pix0 = blockIdx.x * (32 * TILES) + it * 32;
        const int b  = pix0 >> 16;
        const int p0 = pix0 & 65535;
        const int p  = p0 + pj;
        const float fy = (float)(p >> 8), fx = (float)(p & 255);

        // ---------------- phase 1: one (channel, pixel) per thread ----------
        {
            const int c = c_;
            float ndy, ndx;
            if (FIRST) {
                const float* pdy = g_raw + (size_t)(b * OC + 2 * c) * HW;
                const float* pdx = pdy + HW;
                float a0 = g_affa[2 * c],     b0 = g_affb[2 * c];
                float a1 = g_affa[2 * c + 1], b1 = g_affb[2 * c + 1];
                float dy = fmaf(a0, pdy[p], b0);
                float dx = fmaf(a1, pdx[p], b1);
                int i00, i01, i10, i11; float w00, w01, w10, w11;
                bilin_setup(fy + dy, fx + dx, i00, i01, i10, i11, w00, w01, w10, w11);
                float y00 = pdy[i00], y01 = pdy[i01], y10 = pdy[i10], y11 = pdy[i11];
                float x00 = pdx[i00], x01 = pdx[i01], x10 = pdx[i10], x11 = pdx[i11];
                float wdy = w00 * fmaf(a0, y00, b0) + w01 * fmaf(a0, y01, b0)
                          + w10 * fmaf(a0, y10, b0) + w11 * fmaf(a0, y11, b0);
                float wdx = w00 * fmaf(a1, x00, b1) + w01 * fmaf(a1, x01, b1)
                          + w10 * fmaf(a1, x10, b1) + w11 * fmaf(a1, x11, b1);
                ndy = dy + wdy;
                ndx = dx + wdx;
            } else {
                const float2* pc = ((step & 1) ? g_fA : g_fB) + (size_t)(b * IC + c) * HW;
                float2 cv = pc[p];
                float wdy, wdx;
                gather2c(pc, fy + cv.x, fx + cv.y, wdy, wdx);
                ndy = cv.x + wdy;
                ndx = cv.y + wdx;
            }

            if (!LAST) {
                float2* vout = (FIRST ? g_fA : ((step & 1) ? g_fB : g_fA));
                float2 sv; sv.x = ndy; sv.y = ndx;
                vout[(size_t)(b * IC + c) * HW + p] = sv;
            }

            const float* fp = f + (size_t)(b * IC + c) * HW;
            sm_m[c][pj] = gather1c(fp, fy + ndy, fx + ndx);
        }

        __syncthreads();

        // ---------------- phase 2: one (output, pixel) per thread -----------
        {
            const int o = c_;
            float* op = out + (size_t)(b * IC + o) * HW + p;
            float acc = FIRST ? fb_s[o] : *op;
#pragma unroll
            for (int c = 0; c < 16; c++)
                acc += ws[o * 16 + c] * sm_m[c][pj];
            *op = acc;
        }

        if (it + 1 < TILES) __syncthreads();
    }
}

extern "C" void kernel_launch(void* const* d_in, const int* in_sizes, int n_in,
                              void* d_out, int out_size) {
    const float* f     = (const float*)d_in[0];
    const float* vw    = (const float*)d_in[1];
    const float* vb    = (const float*)d_in[2];
    const float* gamma = (const float*)d_in[3];
    const float* beta  = (const float*)d_in[4];
    const float* fw    = (const float*)d_in[5];
    const float* fbias = (const float*)d_in[6];
    float* out = (float*)d_out;

    dim3 cg(8, 32, 8);
    conv_kernel<<<cg, 256>>>(f, vw, vb);
    stats_kernel<<<32, 256>>>(gamma, beta);
    const int nblk = BS * HW / (32 * TILES);   // 8192
    // step 0 writes g_fA; step s>=1: odd reads g_fA->writes g_fB, even reads g_fB->writes g_fA
    step_kernel<true, false><<<nblk, 512>>>(f, fw, fbias, out, 0);
    for (int s = 1; s < NSTEPS - 1; s++)
        step_kernel<false, false><<<nblk, 512>>>(f, fw, fbias, out, s);
    step_kernel<false, true><<<nblk, 512>>>(f, fw, fbias, out, NSTEPS - 1);
}

// round 12
// speedup vs baseline: 1.1301x; 1.1301x over previous
#include <cuda_runtime.h>

#define HH 256
#define WW 256
#define HW 65536
#define BS 8
#define IC 16
#define OC 32
#define NSTEPS 7

typedef unsigned long long u64;

// Scratch (static device globals — no runtime allocation).
__device__ __align__(16) float  g_raw[BS * OC * HW];   // conv output (planar)
__device__ __align__(16) float2 g_fA[BS * IC * HW];    // interleaved flow ping
__device__ __align__(16) float2 g_fB[BS * IC * HW];    // interleaved flow pong
__device__ float g_part[2][OC][2048];                  // per-block partial (sum, sumsq)
__device__ float g_affa[OC];                           // BN affine scale (incl. 1/128)
__device__ float g_affb[OC];                           // BN affine shift (incl. 1/128)

__device__ __forceinline__ u64 pack2(float lo, float hi) {
    u64 r; asm("mov.b64 %0, {%1, %2};" : "=l"(r) : "f"(lo), "f"(hi)); return r;
}
__device__ __forceinline__ void unpack2(u64 v, float& lo, float& hi) {
    asm("mov.b64 {%0, %1}, %2;" : "=f"(lo), "=f"(hi) : "l"(v));
}
__device__ __forceinline__ u64 ffma2(u64 a, u64 b, u64 c) {
    u64 d; asm("fma.rn.f32x2 %0, %1, %2, %3;" : "=l"(d) : "l"(a), "l"(b), "l"(c)); return d;
}

// ---------------------------------------------------------------------------
// Conv 3x3 (16->32, pad 1) via packed f32x2 FMA + deterministic stats.
// ---------------------------------------------------------------------------
__global__ __launch_bounds__(256) void conv_kernel(const float* __restrict__ f,
                                                   const float* __restrict__ vw,
                                                   const float* __restrict__ vb) {
    __shared__ float ft[IC * 10 * 34];
    __shared__ float ws[OC * 144];

    const int tid  = threadIdx.x;
    const int lane = tid & 31;
    const int wid  = tid >> 5;
    const int x0   = blockIdx.x * 32;
    const int y0   = blockIdx.y * 8;
    const int b    = blockIdx.z;

    for (int i = tid; i < OC * 144; i += 256) ws[i] = vw[i];

    const float* fb = f + (size_t)b * IC * HW;
    for (int i = tid; i < IC * 10 * 34; i += 256) {
        int ic = i / 340;
        int rem = i % 340;
        int r = rem / 34, cc = rem % 34;
        int yy = y0 - 1 + r, xx = x0 - 1 + cc;
        float v = 0.f;
        if (yy >= 0 && yy < HH && xx >= 0 && xx < WW) v = fb[ic * HW + yy * WW + xx];
        ft[i] = v;
    }
    __syncthreads();

    const int oc0 = wid * 4;
    u64 acc[4][4];   // 4 oc x 4 pixel-pairs (8 rows)
#pragma unroll
    for (int i = 0; i < 4; i++) {
        float bias = vb[oc0 + i];
        u64 bp = pack2(bias, bias);
#pragma unroll
        for (int j = 0; j < 4; j++) acc[i][j] = bp;
    }

    for (int ic = 0; ic < IC; ic++) {
        const float* ftc = ft + ic * 340;
#pragma unroll
        for (int kx = 0; kx < 3; kx++) {
            float col[10];
#pragma unroll
            for (int r = 0; r < 10; r++) col[r] = ftc[r * 34 + lane + kx];
            u64 colp[9];
#pragma unroll
            for (int r = 0; r < 9; r++) colp[r] = pack2(col[r], col[r + 1]);
#pragma unroll
            for (int i = 0; i < 4; i++) {
#pragma unroll
                for (int ky = 0; ky < 3; ky++) {
                    float w = ws[(oc0 + i) * 144 + ic * 9 + ky * 3 + kx];
                    u64 wd = pack2(w, w);
#pragma unroll
                    for (int j = 0; j < 4; j++)
                        acc[i][j] = ffma2(colp[2 * j + ky], wd, acc[i][j]);
                }
            }
        }
    }

    const int blk = (b * (int)gridDim.y + blockIdx.y) * (int)gridDim.x + blockIdx.x;
#pragma unroll
    for (int i = 0; i < 4; i++) {
        float s = 0.f, s2 = 0.f;
        float* dst = g_raw + (size_t)(b * OC + oc0 + i) * HW + y0 * WW + x0 + lane;
#pragma unroll
        for (int j = 0; j < 4; j++) {
            float v0, v1;
            unpack2(acc[i][j], v0, v1);
            dst[(2 * j) * WW] = v0;
            dst[(2 * j + 1) * WW] = v1;
            s += v0 + v1;
            s2 += v0 * v0 + v1 * v1;
        }
#pragma unroll
        for (int off = 16; off > 0; off >>= 1) {
            s  += __shfl_down_sync(0xffffffffu, s, off);
            s2 += __shfl_down_sync(0xffffffffu, s2, off);
        }
        if (lane == 0) {
            g_part[0][oc0 + i][blk] = s;
            g_part[1][oc0 + i][blk] = s2;
        }
    }
}

// ---------------------------------------------------------------------------
// Reduce partials -> BN affine, folded with 1/2^NSTEPS.
// ---------------------------------------------------------------------------
__global__ __launch_bounds__(256) void stats_kernel(const float* __restrict__ gamma,
                                                    const float* __restrict__ beta) {
    __shared__ float sm[256], sm2[256];
    const int ch = blockIdx.x, tid = threadIdx.x;
    float s = 0.f, s2 = 0.f;
    for (int i = tid; i < 2048; i += 256) {
        s += g_part[0][ch][i];
        s2 += g_part[1][ch][i];
    }
    sm[tid] = s; sm2[tid] = s2;
    __syncthreads();
    for (int off = 128; off > 0; off >>= 1) {
        if (tid < off) { sm[tid] += sm[tid + off]; sm2[tid] += sm2[tid + off]; }
        __syncthreads();
    }
    if (tid == 0) {
        const float n = (float)(BS * HW);
        float mean = sm[0] / n;
        float var = sm2[0] / n - mean * mean;
        float r = rsqrtf(var + 1e-5f);
        const float scale = 1.0f / 128.0f;
        g_affa[ch] = gamma[ch] * r * scale;
        g_affb[ch] = (beta[ch] - gamma[ch] * mean * r) * scale;
    }
}

// ---------------------------------------------------------------------------
// One fused scaling-and-squaring step.
// Block = 512 threads, tile = 64 consecutive pixels; 2 pixels per thread,
// explicitly staged so the two dependent-load chains interleave (MLP 2).
// Phase 1: thread (c, pj) integrates flow channel c at pixels pj, pj+32:
//   stage A: both center loads  stage B: both tap rounds + integrate
//   stage C: both flow stores   stage D: both f gathers -> smem
// Phase 2: thread (o, pj) mixes 16 smem samples for both pixels, RMWs out.
// FIRST reads planar conv output + BN affine per tap, writes out with bias.
// LAST skips the never-read flow store.
// ---------------------------------------------------------------------------
template <bool FIRST, bool LAST>
__global__ __launch_bounds__(512, 3) void step_kernel(const float* __restrict__ f,
                                                      const float* __restrict__ fw,
                                                      const float* __restrict__ fbias,
                                                      float* __restrict__ out,
                                                      int step) {
    __shared__ float ws[256];        // [o][c]
    __shared__ float fb_s[16];
    __shared__ float sm_m[16][65];   // [c][px] padded

    const int tid = threadIdx.x;
    if (tid < 256) {
        int o = tid >> 4, c = tid & 15;
        ws[o * 16 + c] = fw[(o * 16 + c) * NSTEPS + step];
    }
    if (tid < 16) fb_s[tid] = fbias[tid];

    const int pix0 = blockIdx.x * 64;
    const int b  = pix0 >> 16;
    const int p0 = pix0 & 65535;
    const int cc = tid >> 5;
    const int pj = tid & 31;

    // ---------------- phase 1: 2 pixels per (channel) thread ----------------
    {
        const int c = cc;
        const float* pdy = nullptr;
        const float* pdx = nullptr;
        const float2* pc = nullptr;
        float a0 = 0.f, b0 = 0.f, a1 = 0.f, b1 = 0.f;
        if (FIRST) {
            pdy = g_raw + (size_t)(b * OC + 2 * c) * HW;
            pdx = pdy + HW;
            a0 = g_affa[2 * c];     b0 = g_affb[2 * c];
            a1 = g_affa[2 * c + 1]; b1 = g_affb[2 * c + 1];
        } else {
            pc = ((step & 1) ? g_fA : g_fB) + (size_t)(b * IC + c) * HW;
        }

        int   p[2];
        float fy[2], fx[2];
        float dy[2], dx[2];
#pragma unroll
        for (int j = 0; j < 2; j++) {
            p[j]  = p0 + pj + 32 * j;
            fy[j] = (float)(p[j] >> 8);
            fx[j] = (float)(p[j] & 255);
        }

        // stage A: both center loads
#pragma unroll
        for (int j = 0; j < 2; j++) {
            if (FIRST) {
                dy[j] = a0 * pdy[p[j]] + b0;
                dx[j] = a1 * pdx[p[j]] + b1;
            } else {
                float2 cv = pc[p[j]];
                dy[j] = cv.x; dx[j] = cv.y;
            }
        }

        // stage B: both tap rounds + integrate
        float ndy[2], ndx[2];
#pragma unroll
        for (int j = 0; j < 2; j++) {
            float py = fy[j] + dy[j], px = fx[j] + dx[j];
            float yf = floorf(py), xf = floorf(px);
            float wy1 = py - yf, wy0 = 1.f - wy1;
            float wx1 = px - xf, wx0 = 1.f - wx1;
            int yi = (int)yf, xi = (int)xf;
            float wdy = 0.f, wdx = 0.f;
#pragma unroll
            for (int t = 0; t < 4; t++) {
                int ty = yi + (t >> 1), tx = xi + (t & 1);
                float wgt = ((t >> 1) ? wy1 : wy0) * ((t & 1) ? wx1 : wx0);
                if ((unsigned)ty < (unsigned)HH && (unsigned)tx < (unsigned)WW) {
                    int ii = ty * WW + tx;
                    if (FIRST) {
                        wdy += wgt * (a0 * pdy[ii] + b0);
                        wdx += wgt * (a1 * pdx[ii] + b1);
                    } else {
                        float2 v = pc[ii];
                        wdy += wgt * v.x;
                        wdx += wgt * v.y;
                    }
                }
            }
            ndy[j] = dy[j] + wdy;
            ndx[j] = dx[j] + wdx;
        }

        // stage C: both flow stores
        if (!LAST) {
            float2* vout = (FIRST ? g_fA : ((step & 1) ? g_fB : g_fA))
                         + (size_t)(b * IC + c) * HW;
#pragma unroll
            for (int j = 0; j < 2; j++) {
                float2 sv; sv.x = ndy[j]; sv.y = ndx[j];
                vout[p[j]] = sv;
            }
        }

        // stage D: both f gathers -> smem
        const float* fp = f + (size_t)(b * IC + c) * HW;
#pragma unroll
        for (int j = 0; j < 2; j++) {
            float qy = fy[j] + ndy[j], qx = fx[j] + ndx[j];
            float yf = floorf(qy), xf = floorf(qx);
            float vy1 = qy - yf, vy0 = 1.f - vy1;
            float vx1 = qx - xf, vx0 = 1.f - vx1;
            int yi = (int)yf, xi = (int)xf;
            float m = 0.f;
#pragma unroll
            for (int t = 0; t < 4; t++) {
                int ty = yi + (t >> 1), tx = xi + (t & 1);
                float wgt = ((t >> 1) ? vy1 : vy0) * ((t & 1) ? vx1 : vx0);
                if ((unsigned)ty < (unsigned)HH && (unsigned)tx < (unsigned)WW)
                    m += wgt * fp[ty * WW + tx];
            }
            sm_m[c][pj + 32 * j] = m;
        }
    }

    __syncthreads();

    // ---------------- phase 2: 2 pixels per (output) thread -----------------
    {
        const int o = cc;
        float* op = out + (size_t)(b * IC + o) * HW + p0 + pj;

        float acc0 = FIRST ? fb_s[o] : op[0];
        float acc1 = FIRST ? fb_s[o] : op[32];
#pragma unroll
        for (int c = 0; c < 16; c++) {
            float w = ws[o * 16 + c];
            acc0 += w * sm_m[c][pj];
            acc1 += w * sm_m[c][pj + 32];
        }
        op[0]  = acc0;
        op[32] = acc1;
    }
}

extern "C" void kernel_launch(void* const* d_in, const int* in_sizes, int n_in,
                              void* d_out, int out_size) {
    const float* f     = (const float*)d_in[0];
    const float* vw    = (const float*)d_in[1];
    const float* vb    = (const float*)d_in[2];
    const float* gamma = (const float*)d_in[3];
    const float* beta  = (const float*)d_in[4];
    const float* fw    = (const float*)d_in[5];
    const float* fbias = (const float*)d_in[6];
    float* out = (float*)d_out;

    dim3 cg(8, 32, 8);
    conv_kernel<<<cg, 256>>>(f, vw, vb);
    stats_kernel<<<32, 256>>>(gamma, beta);
    const int nblk = BS * HW / 64;   // 8192
    // step 0 writes g_fA; step s>=1: odd reads g_fA->writes g_fB, even reads g_fB->writes g_fA
    step_kernel<true, false><<<nblk, 512>>>(f, fw, fbias, out, 0);
    for (int s = 1; s < NSTEPS - 1; s++)
        step_kernel<false, false><<<nblk, 512>>>(f, fw, fbias, out, s);
    step_kernel<false, true><<<nblk, 512>>>(f, fw, fbias, out, NSTEPS - 1);
}

// round 13
// speedup vs baseline: 1.1883x; 1.0514x over previous
#include <cuda_runtime.h>

#define HH 256
#define WW 256
#define HW 65536
#define BS 8
#define IC 16
#define OC 32
#define NSTEPS 7
#define PXT 4   // pixels per thread in step kernel

typedef unsigned long long u64;

// Scratch (static device globals — no runtime allocation).
__device__ __align__(16) float  g_raw[BS * OC * HW];   // conv output (planar)
__device__ __align__(16) float2 g_fA[BS * IC * HW];    // interleaved flow ping
__device__ __align__(16) float2 g_fB[BS * IC * HW];    // interleaved flow pong
__device__ float g_part[2][OC][2048];                  // per-block partial (sum, sumsq)
__device__ float g_affa[OC];                           // BN affine scale (incl. 1/128)
__device__ float g_affb[OC];                           // BN affine shift (incl. 1/128)

__device__ __forceinline__ u64 pack2(float lo, float hi) {
    u64 r; asm("mov.b64 %0, {%1, %2};" : "=l"(r) : "f"(lo), "f"(hi)); return r;
}
__device__ __forceinline__ void unpack2(u64 v, float& lo, float& hi) {
    asm("mov.b64 {%0, %1}, %2;" : "=f"(lo), "=f"(hi) : "l"(v));
}
__device__ __forceinline__ u64 ffma2(u64 a, u64 b, u64 c) {
    u64 d; asm("fma.rn.f32x2 %0, %1, %2, %3;" : "=l"(d) : "l"(a), "l"(b), "l"(c)); return d;
}

// ---------------------------------------------------------------------------
// Conv 3x3 (16->32, pad 1) via packed f32x2 FMA + deterministic stats.
// ---------------------------------------------------------------------------
__global__ __launch_bounds__(256) void conv_kernel(const float* __restrict__ f,
                                                   const float* __restrict__ vw,
                                                   const float* __restrict__ vb) {
    __shared__ float ft[IC * 10 * 34];
    __shared__ float ws[OC * 144];

    const int tid  = threadIdx.x;
    const int lane = tid & 31;
    const int wid  = tid >> 5;
    const int x0   = blockIdx.x * 32;
    const int y0   = blockIdx.y * 8;
    const int b    = blockIdx.z;

    for (int i = tid; i < OC * 144; i += 256) ws[i] = vw[i];

    const float* fb = f + (size_t)b * IC * HW;
    for (int i = tid; i < IC * 10 * 34; i += 256) {
        int ic = i / 340;
        int rem = i % 340;
        int r = rem / 34, cc = rem % 34;
        int yy = y0 - 1 + r, xx = x0 - 1 + cc;
        float v = 0.f;
        if (yy >= 0 && yy < HH && xx >= 0 && xx < WW) v = fb[ic * HW + yy * WW + xx];
        ft[i] = v;
    }
    __syncthreads();

    const int oc0 = wid * 4;
    u64 acc[4][4];   // 4 oc x 4 pixel-pairs (8 rows)
#pragma unroll
    for (int i = 0; i < 4; i++) {
        float bias = vb[oc0 + i];
        u64 bp = pack2(bias, bias);
#pragma unroll
        for (int j = 0; j < 4; j++) acc[i][j] = bp;
    }

    for (int ic = 0; ic < IC; ic++) {
        const float* ftc = ft + ic * 340;
#pragma unroll
        for (int kx = 0; kx < 3; kx++) {
            float col[10];
#pragma unroll
            for (int r = 0; r < 10; r++) col[r] = ftc[r * 34 + lane + kx];
            u64 colp[9];
#pragma unroll
            for (int r = 0; r < 9; r++) colp[r] = pack2(col[r], col[r + 1]);
#pragma unroll
            for (int i = 0; i < 4; i++) {
#pragma unroll
                for (int ky = 0; ky < 3; ky++) {
                    float w = ws[(oc0 + i) * 144 + ic * 9 + ky * 3 + kx];
                    u64 wd = pack2(w, w);
#pragma unroll
                    for (int j = 0; j < 4; j++)
                        acc[i][j] = ffma2(colp[2 * j + ky], wd, acc[i][j]);
                }
            }
        }
    }

    const int blk = (b * (int)gridDim.y + blockIdx.y) * (int)gridDim.x + blockIdx.x;
#pragma unroll
    for (int i = 0; i < 4; i++) {
        float s = 0.f, s2 = 0.f;
        float* dst = g_raw + (size_t)(b * OC + oc0 + i) * HW + y0 * WW + x0 + lane;
#pragma unroll
        for (int j = 0; j < 4; j++) {
            float v0, v1;
            unpack2(acc[i][j], v0, v1);
            dst[(2 * j) * WW] = v0;
            dst[(2 * j + 1) * WW] = v1;
            s += v0 + v1;
            s2 += v0 * v0 + v1 * v1;
        }
#pragma unroll
        for (int off = 16; off > 0; off >>= 1) {
            s  += __shfl_down_sync(0xffffffffu, s, off);
            s2 += __shfl_down_sync(0xffffffffu, s2, off);
        }
        if (lane == 0) {
            g_part[0][oc0 + i][blk] = s;
            g_part[1][oc0 + i][blk] = s2;
        }
    }
}

// ---------------------------------------------------------------------------
// Reduce partials -> BN affine, folded with 1/2^NSTEPS.
// ---------------------------------------------------------------------------
__global__ __launch_bounds__(256) void stats_kernel(const float* __restrict__ gamma,
                                                    const float* __restrict__ beta) {
    __shared__ float sm[256], sm2[256];
    const int ch = blockIdx.x, tid = threadIdx.x;
    float s = 0.f, s2 = 0.f;
    for (int i = tid; i < 2048; i += 256) {
        s += g_part[0][ch][i];
        s2 += g_part[1][ch][i];
    }
    sm[tid] = s; sm2[tid] = s2;
    __syncthreads();
    for (int off = 128; off > 0; off >>= 1) {
        if (tid < off) { sm[tid] += sm[tid + off]; sm2[tid] += sm2[tid + off]; }
        __syncthreads();
    }
    if (tid == 0) {
        const float n = (float)(BS * HW);
        float mean = sm[0] / n;
        float var = sm2[0] / n - mean * mean;
        float r = rsqrtf(var + 1e-5f);
        const float scale = 1.0f / 128.0f;
        g_affa[ch] = gamma[ch] * r * scale;
        g_affb[ch] = (beta[ch] - gamma[ch] * mean * r) * scale;
    }
}

// ---------------------------------------------------------------------------
// One fused scaling-and-squaring step.
// Block = 512 threads, tile = 32*PXT consecutive pixels; PXT pixels/thread,
// staged so the PXT dependent-load chains interleave (MLP = PXT).
// Phase 1: thread (c, pj) integrates flow channel c at pixels pj + 32*j:
//   stage A: all center loads   stage B: all tap rounds + integrate
//   stage C: all flow stores    stage D: all f gathers -> smem
// Phase 2: thread (o, pj) mixes 16 smem samples for PXT pixels, RMWs out.
// FIRST reads planar conv output + BN affine per tap, writes out with bias.
// LAST skips the never-read flow store.
// ---------------------------------------------------------------------------
template <bool FIRST, bool LAST>
__global__ __launch_bounds__(512, 2) void step_kernel(const float* __restrict__ f,
                                                      const float* __restrict__ fw,
                                                      const float* __restrict__ fbias,
                                                      float* __restrict__ out,
                                                      int step) {
    __shared__ float ws[256];               // [o][c]
    __shared__ float fb_s[16];
    __shared__ float sm_m[16][32 * PXT + 1]; // [c][px] padded

    const int tid = threadIdx.x;
    if (tid < 256) {
        int o = tid >> 4, c = tid & 15;
        ws[o * 16 + c] = fw[(o * 16 + c) * NSTEPS + step];
    }
    if (tid < 16) fb_s[tid] = fbias[tid];

    const int pix0 = blockIdx.x * (32 * PXT);
    const int b  = pix0 >> 16;
    const int p0 = pix0 & 65535;
    const int cc = tid >> 5;
    const int pj = tid & 31;

    // ---------------- phase 1: PXT pixels per (channel) thread --------------
    {
        const int c = cc;
        const float* pdy = nullptr;
        const float* pdx = nullptr;
        const float2* pc = nullptr;
        float a0 = 0.f, b0 = 0.f, a1 = 0.f, b1 = 0.f;
        if (FIRST) {
            pdy = g_raw + (size_t)(b * OC + 2 * c) * HW;
            pdx = pdy + HW;
            a0 = g_affa[2 * c];     b0 = g_affb[2 * c];
            a1 = g_affa[2 * c + 1]; b1 = g_affb[2 * c + 1];
        } else {
            pc = ((step & 1) ? g_fA : g_fB) + (size_t)(b * IC + c) * HW;
        }

        float dy[PXT], dx[PXT];

        // stage A: all center loads
#pragma unroll
        for (int j = 0; j < PXT; j++) {
            int p = p0 + pj + 32 * j;
            if (FIRST) {
                dy[j] = a0 * pdy[p] + b0;
                dx[j] = a1 * pdx[p] + b1;
            } else {
                float2 cv = pc[p];
                dy[j] = cv.x; dx[j] = cv.y;
            }
        }

        // stage B: all tap rounds + integrate
        float ndy[PXT], ndx[PXT];
#pragma unroll
        for (int j = 0; j < PXT; j++) {
            int p = p0 + pj + 32 * j;
            float fy = (float)(p >> 8), fx = (float)(p & 255);
            float py = fy + dy[j], px = fx + dx[j];
            float yf = floorf(py), xf = floorf(px);
            float wy1 = py - yf, wy0 = 1.f - wy1;
            float wx1 = px - xf, wx0 = 1.f - wx1;
            int yi = (int)yf, xi = (int)xf;
            float wdy = 0.f, wdx = 0.f;
#pragma unroll
            for (int t = 0; t < 4; t++) {
                int ty = yi + (t >> 1), tx = xi + (t & 1);
                float wgt = ((t >> 1) ? wy1 : wy0) * ((t & 1) ? wx1 : wx0);
                if ((unsigned)ty < (unsigned)HH && (unsigned)tx < (unsigned)WW) {
                    int ii = ty * WW + tx;
                    if (FIRST) {
                        wdy += wgt * (a0 * pdy[ii] + b0);
                        wdx += wgt * (a1 * pdx[ii] + b1);
                    } else {
                        float2 v = pc[ii];
                        wdy += wgt * v.x;
                        wdx += wgt * v.y;
                    }
                }
            }
            ndy[j] = dy[j] + wdy;
            ndx[j] = dx[j] + wdx;
        }

        // stage C: all flow stores
        if (!LAST) {
            float2* vout = (FIRST ? g_fA : ((step & 1) ? g_fB : g_fA))
                         + (size_t)(b * IC + c) * HW;
#pragma unroll
            for (int j = 0; j < PXT; j++) {
                float2 sv; sv.x = ndy[j]; sv.y = ndx[j];
                vout[p0 + pj + 32 * j] = sv;
            }
        }

        // stage D: all f gathers -> smem
        const float* fp = f + (size_t)(b * IC + c) * HW;
#pragma unroll
        for (int j = 0; j < PXT; j++) {
            int p = p0 + pj + 32 * j;
            float fy = (float)(p >> 8), fx = (float)(p & 255);
            float qy = fy + ndy[j], qx = fx + ndx[j];
            float yf = floorf(qy), xf = floorf(qx);
            float vy1 = qy - yf, vy0 = 1.f - vy1;
            float vx1 = qx - xf, vx0 = 1.f - vx1;
            int yi = (int)yf, xi = (int)xf;
            float m = 0.f;
#pragma unroll
            for (int t = 0; t < 4; t++) {
                int ty = yi + (t >> 1), tx = xi + (t & 1);
                float wgt = ((t >> 1) ? vy1 : vy0) * ((t & 1) ? vx1 : vx0);
                if ((unsigned)ty < (unsigned)HH && (unsigned)tx < (unsigned)WW)
                    m += wgt * fp[ty * WW + tx];
            }
            sm_m[c][pj + 32 * j] = m;
        }
    }

    __syncthreads();

    // ---------------- phase 2: PXT pixels per (output) thread ---------------
    {
        const int o = cc;
        float* op = out + (size_t)(b * IC + o) * HW + p0 + pj;

        float acc[PXT];
#pragma unroll
        for (int j = 0; j < PXT; j++)
            acc[j] = FIRST ? fb_s[o] : op[32 * j];
#pragma unroll
        for (int c = 0; c < 16; c++) {
            float w = ws[o * 16 + c];
#pragma unroll
            for (int j = 0; j < PXT; j++)
                acc[j] += w * sm_m[c][pj + 32 * j];
        }
#pragma unroll
        for (int j = 0; j < PXT; j++)
            op[32 * j] = acc[j];
    }
}

extern "C" void kernel_launch(void* const* d_in, const int* in_sizes, int n_in,
                              void* d_out, int out_size) {
    const float* f     = (const float*)d_in[0];
    const float* vw    = (const float*)d_in[1];
    const float* vb    = (const float*)d_in[2];
    const float* gamma = (const float*)d_in[3];
    const float* beta  = (const float*)d_in[4];
    const float* fw    = (const float*)d_in[5];
    const float* fbias = (const float*)d_in[6];
    float* out = (float*)d_out;

    dim3 cg(8, 32, 8);
    conv_kernel<<<cg, 256>>>(f, vw, vb);
    stats_kernel<<<32, 256>>>(gamma, beta);
    const int nblk = BS * HW / (32 * PXT);   // 4096
    // step 0 writes g_fA; step s>=1: odd reads g_fA->writes g_fB, even reads g_fB->writes g_fA
    step_kernel<true, false><<<nblk, 512>>>(f, fw, fbias, out, 0);
    for (int s = 1; s < NSTEPS - 1; s++)
        step_kernel<false, false><<<nblk, 512>>>(f, fw, fbias, out, s);
    step_kernel<false, true><<<nblk, 512>>>(f, fw, fbias, out, NSTEPS - 1);
}